// round 12
// baseline (speedup 1.0000x reference)
#include <cuda_runtime.h>
#include <cuda_bf16.h>
#include <cstdint>
#include <math.h>

#define Bn 32
#define Rn 512
#define Dn 256
#define Pn 5532
#define SLOT 512
#define NROWS (Bn*Rn)
#define PAD 72                 // bf16 row stride in smem (64 + 8)
#define STAGE_ELE (128*PAD)    // elements per tile per stage

// ---------------- scratch ----------------
__device__ __align__(16) __nv_bfloat16 g_xh[NROWS*Dn];       // scaled feats bf16  8MB
__device__ __align__(16) __nv_bfloat16 g_ph[Bn*SLOT*Dn];     // normed protos bf16 8MB
__device__ __align__(16) float g_pm[NROWS*4];                // per-chunk row max
__device__ __align__(16) float g_ps[NROWS*4];                // per-chunk row sumexp
__device__ float g_tgt[NROWS];                               // target logit
__device__ int   g_rslot[NROWS];                             // roi -> slot (-1 bg)
__device__ int   g_sorted[NROWS];                            // rois sorted by slot (per image)
__device__ int   g_cnt[Bn*SLOT];                             // count per slot
__device__ int   g_cstart[Bn*SLOT];                          // member start per slot
__device__ int   g_nuniq[Bn];
__device__ float g_rgsum[Bn*4];                              // per-rowgroup nll sum
__device__ int   g_rgcnt[Bn*4];                              // per-rowgroup valid count
__device__ unsigned g_rgt[Bn*4];                             // row-group tickets (start 0)
__device__ unsigned g_ft;                                    // final ticket (start 0)

// ---------------- helpers ----------------
__device__ __forceinline__ uint32_t smem_u32(const void* p) {
    uint32_t a;
    asm("{ .reg .u64 t; cvta.to.shared.u64 t, %1; cvt.u32.u64 %0, t; }" : "=r"(a) : "l"(p));
    return a;
}
__device__ __forceinline__ void cp16(uint32_t dst, const void* src) {
    asm volatile("cp.async.cg.shared.global [%0], [%1], 16;" :: "r"(dst), "l"(src));
}
__device__ __forceinline__ void cp_commit() {
    asm volatile("cp.async.commit_group;" ::: "memory");
}
template<int N> __device__ __forceinline__ void cp_wait() {
    asm volatile("cp.async.wait_group %0;" :: "n"(N) : "memory");
}
__device__ __forceinline__ void ldm_x4(uint32_t* r, uint32_t addr) {
    asm volatile("ldmatrix.sync.aligned.m8n8.x4.shared.b16 {%0,%1,%2,%3}, [%4];"
        : "=r"(r[0]), "=r"(r[1]), "=r"(r[2]), "=r"(r[3]) : "r"(addr));
}
__device__ __forceinline__ void mma_bf16(float* c, const uint32_t* a, uint32_t b0, uint32_t b1) {
    asm volatile(
        "mma.sync.aligned.m16n8k16.row.col.f32.bf16.bf16.f32 "
        "{%0,%1,%2,%3}, {%4,%5,%6,%7}, {%8,%9}, {%0,%1,%2,%3};"
        : "+f"(c[0]), "+f"(c[1]), "+f"(c[2]), "+f"(c[3])
        : "r"(a[0]), "r"(a[1]), "r"(a[2]), "r"(a[3]), "r"(b0), "r"(b1));
}
__device__ __forceinline__ unsigned long long pack4bf(float a, float b, float c, float d) {
    __nv_bfloat162 lo = __floats2bfloat162_rn(a, b);
    __nv_bfloat162 hi = __floats2bfloat162_rn(c, d);
    unsigned int l = *reinterpret_cast<unsigned int*>(&lo);
    unsigned int h = *reinterpret_cast<unsigned int*>(&hi);
    return (unsigned long long)l | ((unsigned long long)h << 32);
}

// ---------------- 1: fused [compact (blocks 0..31)] + [scale (blocks 32..2079)] -------
__global__ void k_prep_compact(const float* __restrict__ inp, const float* __restrict__ cls,
                               const int* __restrict__ roi_label) {
    __shared__ int cnt[Pn];          // counts, then pid -> slot id
    __shared__ int wU[8], wC[8];
    __shared__ int s_cur[SLOT];

    if (blockIdx.x >= Bn) {
        // ---- scale path: g_xh = bf16(inputs * cls) ----
        int i = (blockIdx.x - Bn) * 256 + threadIdx.x;   // float4 index
        int row = i >> 6;
        float c = cls[row];
        float4 v = ((const float4*)inp)[i];
        ((unsigned long long*)g_xh)[i] = pack4bf(v.x * c, v.y * c, v.z * c, v.w * c);
        return;
    }

    // ---- compact path ----
    int b = blockIdx.x;
    int tid = threadIdx.x;
    for (int p = tid; p < Pn; p += 256) cnt[p] = 0;
    __syncthreads();
    for (int r = tid; r < Rn; r += 256) {
        int lab = roi_label[b*Rn + r] - 1;
        if (lab >= 0) atomicAdd(&cnt[lab], 1);
    }
    __syncthreads();
    const int chunk = (Pn + 255) / 256;   // 22
    int start = tid * chunk;
    int lu = 0, lc = 0;
    for (int i = 0; i < chunk; i++) {
        int p = start + i;
        if (p < Pn) { int c = cnt[p]; if (c > 0) { lu++; lc += c; } }
    }
    // parallel exclusive scan over 256 threads (both lu and lc)
    int wlane = tid & 31, wwarp = tid >> 5;
    int iu = lu, ic = lc;
    #pragma unroll
    for (int o = 1; o < 32; o <<= 1) {
        int tu = __shfl_up_sync(0xffffffffu, iu, o);
        int tc = __shfl_up_sync(0xffffffffu, ic, o);
        if (wlane >= o) { iu += tu; ic += tc; }
    }
    if (wlane == 31) { wU[wwarp] = iu; wC[wwarp] = ic; }
    __syncthreads();
    if (tid == 0) {
        int au = 0, ac = 0;
        #pragma unroll
        for (int w = 0; w < 8; w++) {
            int tu = wU[w], tc = wC[w];
            wU[w] = au; wC[w] = ac;
            au += tu; ac += tc;
        }
        g_nuniq[b] = au;
    }
    __syncthreads();
    int off = iu - lu + wU[wwarp];     // exclusive prefix of unique-count
    int cst = ic - lc + wC[wwarp];     // exclusive prefix of member-count
    for (int i = 0; i < chunk; i++) {
        int p = start + i;
        if (p >= Pn) break;
        int c = cnt[p];
        if (c > 0) {
            g_cnt[b*SLOT + off]    = c;
            g_cstart[b*SLOT + off] = cst;
            s_cur[off] = cst;
            cnt[p] = off;
            off++; cst += c;
        } else {
            cnt[p] = -1;
        }
    }
    __syncthreads();
    for (int r = tid; r < Rn; r += 256) {
        int lab = roi_label[b*Rn + r] - 1;
        int slot = (lab >= 0) ? cnt[lab] : -1;
        g_rslot[b*Rn + r] = slot;
        if (slot >= 0) {
            int pos = atomicAdd(&s_cur[slot], 1);
            g_sorted[b*Rn + pos] = r;
        }
    }
}

// ---------------- 2: proto gather + normalize -> bf16 (one warp per slot) ----------------
__global__ void k_norm() {
    int idx  = blockIdx.x * 8 + (threadIdx.x >> 5);
    int lane = threadIdx.x & 31;
    int b = idx / SLOT, j = idx % SLOT;
    uint4* dst = (uint4*)(g_ph + (size_t)idx * Dn);   // 32 lanes x 16B = 512B row
    if (j >= g_nuniq[b]) {
        dst[lane] = make_uint4(0, 0, 0, 0);
        return;
    }
    int c  = g_cnt[b*SLOT + j];
    int st = g_cstart[b*SLOT + j];
    float acc[8];
    #pragma unroll
    for (int q = 0; q < 8; q++) acc[q] = 0.f;
    for (int m = 0; m < c; m++) {
        int r = g_sorted[b*Rn + st + m];
        uint4 v = ((const uint4*)(g_xh + (size_t)(b*Rn + r) * Dn))[lane];
        uint32_t w[4] = {v.x, v.y, v.z, v.w};
        #pragma unroll
        for (int q = 0; q < 4; q++) {
            float2 f = __bfloat1622float2(*(__nv_bfloat162*)&w[q]);
            acc[q*2]   += f.x;
            acc[q*2+1] += f.y;
        }
    }
    float ss = 0.f;
    #pragma unroll
    for (int q = 0; q < 8; q++) ss += acc[q]*acc[q];
    #pragma unroll
    for (int o = 16; o > 0; o >>= 1) ss += __shfl_xor_sync(0xffffffffu, ss, o);
    float cf = (float)c;
    float scale = 1.0f / (cf * fmaxf(sqrtf(ss) / cf, 1e-12f));
    uint32_t o0, o1, o2, o3;
    {
        __nv_bfloat162 p0 = __floats2bfloat162_rn(acc[0]*scale, acc[1]*scale);
        __nv_bfloat162 p1 = __floats2bfloat162_rn(acc[2]*scale, acc[3]*scale);
        __nv_bfloat162 p2 = __floats2bfloat162_rn(acc[4]*scale, acc[5]*scale);
        __nv_bfloat162 p3 = __floats2bfloat162_rn(acc[6]*scale, acc[7]*scale);
        o0 = *(uint32_t*)&p0; o1 = *(uint32_t*)&p1; o2 = *(uint32_t*)&p2; o3 = *(uint32_t*)&p3;
    }
    dst[lane] = make_uint4(o0, o1, o2, o3);
}

// ---------------- 3: bf16 mma.sync GEMM + fused softmax + ticketed final reduce ------
__global__ __launch_bounds__(256, 2) void k_gemm_mma(float* __restrict__ out) {
    extern __shared__ __nv_bfloat16 smem[];      // [2][sA 128*PAD | sB 128*PAD]
    __shared__ int   s_jt[128];
    __shared__ float s_m[4][128];
    __shared__ float s_s[4][128];
    __shared__ int   s_last;
    __shared__ float s_rs[8];
    __shared__ int   s_rc[8];
    int tid = threadIdx.x;
    int warp = tid >> 5, lane = tid & 31;
    int b = blockIdx.z;
    int rBase = blockIdx.y * 128;
    int jBase = blockIdx.x * 128;
    int rg = b * 4 + blockIdx.y;                 // row-group id
    const __nv_bfloat16* A  = g_xh + ((size_t)b*Rn   + rBase) * Dn;
    const __nv_bfloat16* Bp = g_ph + ((size_t)b*SLOT + jBase) * Dn;

    if (tid < 128) s_jt[tid] = g_rslot[b*Rn + rBase + tid];

    int wm = (warp >> 2) * 64;      // 0 / 64
    int wn = (warp & 3) * 32;       // 0 / 32 / 64 / 96
    int wq = warp & 3;

    float acc[4][4][4];
    #pragma unroll
    for (int mt = 0; mt < 4; mt++)
        #pragma unroll
        for (int nt = 0; nt < 4; nt++)
            #pragma unroll
            for (int q = 0; q < 4; q++) acc[mt][nt][q] = 0.f;

    uint32_t sBase = smem_u32(smem);
    const uint32_t stageBytes = 2u * STAGE_ELE * 2u;  // A+B per stage
    const uint32_t sBoff = STAGE_ELE * 2u;

    int aRow = (lane & 15);
    int aColOff = (lane >> 4) * 8;
    int bN = (lane & 7) + ((lane >> 4) << 3);
    int bKOff = ((lane >> 3) & 1) * 8;

    int srow[4], scol[4];
    #pragma unroll
    for (int jj = 0; jj < 4; jj++) {
        int i = tid + jj*256;
        srow[jj] = i >> 3; scol[jj] = i & 7;
    }

    #define ISSUE(kc, stg) { \
        uint32_t d0 = sBase + (stg)*stageBytes; \
        _Pragma("unroll") \
        for (int jj = 0; jj < 4; jj++) { \
            uint32_t off = (srow[jj]*PAD + scol[jj]*8) * 2; \
            cp16(d0 + off,          A  + (size_t)srow[jj]*Dn + (kc)*64 + scol[jj]*8); \
            cp16(d0 + sBoff + off,  Bp + (size_t)srow[jj]*Dn + (kc)*64 + scol[jj]*8); \
        } \
        cp_commit(); \
    }

    ISSUE(0, 0);
    for (int kc = 0; kc < 4; kc++) {
        if (kc) __syncthreads();
        if (kc < 3) ISSUE(kc + 1, (kc + 1) & 1);
        if (kc < 3) cp_wait<1>(); else cp_wait<0>();
        __syncthreads();
        uint32_t sAu = sBase + (kc & 1)*stageBytes;
        uint32_t sBu = sAu + sBoff;
        #pragma unroll
        for (int ks = 0; ks < 4; ks++) {
            int kk = ks * 16;
            uint32_t a[4][4];
            #pragma unroll
            for (int mt = 0; mt < 4; mt++) {
                int row = wm + mt*16 + aRow;
                ldm_x4(a[mt], sAu + (row*PAD + kk + aColOff) * 2);
            }
            uint32_t bb[2][4];
            #pragma unroll
            for (int p = 0; p < 2; p++) {
                int n = wn + p*16 + bN;
                ldm_x4(bb[p], sBu + (n*PAD + kk + bKOff) * 2);
            }
            #pragma unroll
            for (int mt = 0; mt < 4; mt++)
                #pragma unroll
                for (int nt = 0; nt < 4; nt++)
                    mma_bf16(acc[mt][nt], a[mt],
                             bb[nt >> 1][(nt & 1)*2], bb[nt >> 1][(nt & 1)*2 + 1]);
        }
    }

    // ---- fused epilogue: per-row partial (max, sumexp) over this 128-col chunk ----
    int nu = g_nuniq[b];
    int tg = lane >> 2, ti = lane & 3;
    #pragma unroll
    for (int mt = 0; mt < 4; mt++) {
        #pragma unroll
        for (int h = 0; h < 2; h++) {
            int rowL = wm + mt*16 + tg + h*8;
            int jt = s_jt[rowL];
            float vals[8];
            float vmax = -1e30f;
            #pragma unroll
            for (int nt = 0; nt < 4; nt++) {
                #pragma unroll
                for (int ql = 0; ql < 2; ql++) {
                    int j = jBase + wn + nt*8 + ti*2 + ql;
                    float v = acc[mt][nt][h*2 + ql];
                    if (j == jt) g_tgt[b*Rn + rBase + rowL] = v;
                    float vv = (j < nu) ? v : -1e30f;
                    vals[nt*2 + ql] = vv;
                    vmax = fmaxf(vmax, vv);
                }
            }
            vmax = fmaxf(vmax, __shfl_xor_sync(0xffffffffu, vmax, 1));
            vmax = fmaxf(vmax, __shfl_xor_sync(0xffffffffu, vmax, 2));
            float se = 0.f;
            #pragma unroll
            for (int q = 0; q < 8; q++) se += __expf(vals[q] - vmax);
            se += __shfl_xor_sync(0xffffffffu, se, 1);
            se += __shfl_xor_sync(0xffffffffu, se, 2);
            if (ti == 0) { s_m[wq][rowL] = vmax; s_s[wq][rowL] = se; }
        }
    }
    __syncthreads();
    if (tid < 128) {
        float m0 = s_m[0][tid], m1 = s_m[1][tid], m2 = s_m[2][tid], m3 = s_m[3][tid];
        float m = fmaxf(fmaxf(m0, m1), fmaxf(m2, m3));
        float s = s_s[0][tid]*__expf(m0 - m) + s_s[1][tid]*__expf(m1 - m)
                + s_s[2][tid]*__expf(m2 - m) + s_s[3][tid]*__expf(m3 - m);
        int roi = b*Rn + rBase + tid;
        g_pm[roi*4 + blockIdx.x] = m;
        g_ps[roi*4 + blockIdx.x] = s;
    }
    __syncthreads();

    // ---- ticket: 4th chunk-CTA of this row-group finishes the 128 rows ----
    if (tid == 0) {
        __threadfence();
        unsigned old = atomicAdd(&g_rgt[rg], 1u);
        s_last = (old == 3u);
    }
    __syncthreads();
    if (!s_last) return;
    __threadfence();                      // acquire: see peers' pm/ps/tgt

    float sum = 0.f; int cnt = 0;
    if (tid < 128) {
        int i = b*Rn + rBase + tid;
        if (s_jt[tid] >= 0) {
            float4 pm = *(const float4*)&g_pm[i*4];
            float4 ps = *(const float4*)&g_ps[i*4];
            float m = fmaxf(fmaxf(pm.x, pm.y), fmaxf(pm.z, pm.w));
            float s = ps.x*__expf(pm.x - m) + ps.y*__expf(pm.y - m)
                    + ps.z*__expf(pm.z - m) + ps.w*__expf(pm.w - m);
            sum = (m + logf(s)) - g_tgt[i];
            cnt = 1;
        }
    }
    #pragma unroll
    for (int o = 16; o > 0; o >>= 1) {
        sum += __shfl_xor_sync(0xffffffffu, sum, o);
        cnt += __shfl_xor_sync(0xffffffffu, cnt, o);
    }
    if (lane == 0) { s_rs[warp] = sum; s_rc[warp] = cnt; }
    __syncthreads();
    if (tid == 0) {
        float ts = 0.f; int tc = 0;
        #pragma unroll
        for (int w = 0; w < 4; w++) { ts += s_rs[w]; tc += s_rc[w]; }  // only warps 0-3 hold rows
        g_rgsum[rg] = ts; g_rgcnt[rg] = tc;
        __threadfence();
        unsigned old = atomicAdd(&g_ft, 1u);
        if (old == (unsigned)(Bn*4 - 1)) {
            __threadfence();
            float fs = 0.f; int fc = 0;
            for (int i = 0; i < Bn*4; i++) { fs += g_rgsum[i]; fc += g_rgcnt[i]; }
            out[0] = fs / fmaxf((float)fc, 1.0f);
            // reset tickets for next graph replay
            for (int i = 0; i < Bn*4; i++) g_rgt[i] = 0u;
            g_ft = 0u;
        }
    }
}

extern "C" void kernel_launch(void* const* d_in, const int* in_sizes, int n_in,
                              void* d_out, int out_size) {
    const float* inp = (const float*)d_in[0];
    const float* cls = (const float*)d_in[1];
    const int*   lab = (const int*)d_in[2];
    float* out = (float*)d_out;

    const int gemmSmem = 2 * 2 * STAGE_ELE * 2;  // 73728 bytes
    cudaFuncSetAttribute(k_gemm_mma, cudaFuncAttributeMaxDynamicSharedMemorySize, gemmSmem);

    k_prep_compact<<<Bn + NROWS*Dn/4/256, 256>>>(inp, cls, lab);
    k_norm<<<Bn*SLOT/8, 256>>>();
    k_gemm_mma<<<dim3(SLOT/128, Rn/128, Bn), 256, gemmSmem>>>(out);
}

// round 13
// speedup vs baseline: 1.1057x; 1.1057x over previous
#include <cuda_runtime.h>
#include <cuda_bf16.h>
#include <cstdint>
#include <math.h>

#define Bn 32
#define Rn 512
#define Dn 256
#define Pn 5532
#define SLOT 512
#define NROWS (Bn*Rn)
#define PAD 72                 // bf16 row stride in smem (64 + 8)
#define STAGE_ELE (128*PAD)    // elements per tile per stage

// ---------------- scratch ----------------
__device__ __align__(16) __nv_bfloat16 g_xh[NROWS*Dn];       // scaled feats bf16  8MB
__device__ __align__(16) __nv_bfloat16 g_ph[Bn*SLOT*Dn];     // normed protos bf16 8MB
__device__ __align__(16) float g_pm[NROWS*4];                // per-chunk row max
__device__ __align__(16) float g_ps[NROWS*4];                // per-chunk row sumexp
__device__ float g_tgt[NROWS];                               // target logit
__device__ int   g_rslot[NROWS];                             // roi -> slot (-1 bg)
__device__ int   g_sorted[NROWS];                            // rois sorted by slot (per image)
__device__ int   g_cnt[Bn*SLOT];                             // count per slot
__device__ int   g_cstart[Bn*SLOT];                          // member start per slot
__device__ int   g_nuniq[Bn];
__device__ float g_bsum[Bn];                                 // per-image nll sum
__device__ int   g_bcnt[Bn];                                 // per-image valid count

// ---------------- helpers ----------------
__device__ __forceinline__ uint32_t smem_u32(const void* p) {
    uint32_t a;
    asm("{ .reg .u64 t; cvta.to.shared.u64 t, %1; cvt.u32.u64 %0, t; }" : "=r"(a) : "l"(p));
    return a;
}
__device__ __forceinline__ void cp16(uint32_t dst, const void* src) {
    asm volatile("cp.async.cg.shared.global [%0], [%1], 16;" :: "r"(dst), "l"(src));
}
__device__ __forceinline__ void cp_commit() {
    asm volatile("cp.async.commit_group;" ::: "memory");
}
template<int N> __device__ __forceinline__ void cp_wait() {
    asm volatile("cp.async.wait_group %0;" :: "n"(N) : "memory");
}
__device__ __forceinline__ void ldm_x4(uint32_t* r, uint32_t addr) {
    asm volatile("ldmatrix.sync.aligned.m8n8.x4.shared.b16 {%0,%1,%2,%3}, [%4];"
        : "=r"(r[0]), "=r"(r[1]), "=r"(r[2]), "=r"(r[3]) : "r"(addr));
}
__device__ __forceinline__ void mma_bf16(float* c, const uint32_t* a, uint32_t b0, uint32_t b1) {
    asm volatile(
        "mma.sync.aligned.m16n8k16.row.col.f32.bf16.bf16.f32 "
        "{%0,%1,%2,%3}, {%4,%5,%6,%7}, {%8,%9}, {%0,%1,%2,%3};"
        : "+f"(c[0]), "+f"(c[1]), "+f"(c[2]), "+f"(c[3])
        : "r"(a[0]), "r"(a[1]), "r"(a[2]), "r"(a[3]), "r"(b0), "r"(b1));
}
__device__ __forceinline__ unsigned long long pack4bf(float a, float b, float c, float d) {
    __nv_bfloat162 lo = __floats2bfloat162_rn(a, b);
    __nv_bfloat162 hi = __floats2bfloat162_rn(c, d);
    unsigned int l = *reinterpret_cast<unsigned int*>(&lo);
    unsigned int h = *reinterpret_cast<unsigned int*>(&hi);
    return (unsigned long long)l | ((unsigned long long)h << 32);
}

// ---------------- 1: fused [compact (blocks 0..31)] + [scale (blocks 32..1055)] -------
// scale path: 4 independent float4 loads per thread (MLP=4) to hide DRAM latency.
__global__ void k_prep_compact(const float* __restrict__ inp, const float* __restrict__ cls,
                               const int* __restrict__ roi_label) {
    __shared__ int cnt[Pn];          // counts, then pid -> slot id
    __shared__ int wU[8], wC[8];
    __shared__ int s_cur[SLOT];

    if (blockIdx.x >= Bn) {
        // ---- scale path: g_xh = bf16(inputs * cls) ----
        int base = (blockIdx.x - Bn) * 1024 + threadIdx.x;   // float4 index, 4 per thread
        float4 v[4]; float c[4]; int idx[4];
        #pragma unroll
        for (int q = 0; q < 4; q++) {
            idx[q] = base + q*256;
            v[q] = ((const float4*)inp)[idx[q]];
        }
        #pragma unroll
        for (int q = 0; q < 4; q++) c[q] = cls[idx[q] >> 6];
        #pragma unroll
        for (int q = 0; q < 4; q++) {
            ((unsigned long long*)g_xh)[idx[q]] =
                pack4bf(v[q].x*c[q], v[q].y*c[q], v[q].z*c[q], v[q].w*c[q]);
        }
        return;
    }

    // ---- compact path ----
    int b = blockIdx.x;
    int tid = threadIdx.x;
    for (int p = tid; p < Pn; p += 256) cnt[p] = 0;
    __syncthreads();
    for (int r = tid; r < Rn; r += 256) {
        int lab = roi_label[b*Rn + r] - 1;
        if (lab >= 0) atomicAdd(&cnt[lab], 1);
    }
    __syncthreads();
    const int chunk = (Pn + 255) / 256;   // 22
    int start = tid * chunk;
    int lu = 0, lc = 0;
    for (int i = 0; i < chunk; i++) {
        int p = start + i;
        if (p < Pn) { int c = cnt[p]; if (c > 0) { lu++; lc += c; } }
    }
    // parallel exclusive scan over 256 threads (both lu and lc)
    int wlane = tid & 31, wwarp = tid >> 5;
    int iu = lu, ic = lc;
    #pragma unroll
    for (int o = 1; o < 32; o <<= 1) {
        int tu = __shfl_up_sync(0xffffffffu, iu, o);
        int tc = __shfl_up_sync(0xffffffffu, ic, o);
        if (wlane >= o) { iu += tu; ic += tc; }
    }
    if (wlane == 31) { wU[wwarp] = iu; wC[wwarp] = ic; }
    __syncthreads();
    if (tid == 0) {
        int au = 0, ac = 0;
        #pragma unroll
        for (int w = 0; w < 8; w++) {
            int tu = wU[w], tc = wC[w];
            wU[w] = au; wC[w] = ac;
            au += tu; ac += tc;
        }
        g_nuniq[b] = au;
    }
    __syncthreads();
    int off = iu - lu + wU[wwarp];     // exclusive prefix of unique-count
    int cst = ic - lc + wC[wwarp];     // exclusive prefix of member-count
    for (int i = 0; i < chunk; i++) {
        int p = start + i;
        if (p >= Pn) break;
        int c = cnt[p];
        if (c > 0) {
            g_cnt[b*SLOT + off]    = c;
            g_cstart[b*SLOT + off] = cst;
            s_cur[off] = cst;
            cnt[p] = off;
            off++; cst += c;
        } else {
            cnt[p] = -1;
        }
    }
    __syncthreads();
    for (int r = tid; r < Rn; r += 256) {
        int lab = roi_label[b*Rn + r] - 1;
        int slot = (lab >= 0) ? cnt[lab] : -1;
        g_rslot[b*Rn + r] = slot;
        if (slot >= 0) {
            int pos = atomicAdd(&s_cur[slot], 1);
            g_sorted[b*Rn + pos] = r;
        }
    }
}

// ---------------- 2: proto gather + normalize -> bf16 (one warp per slot) ----------------
__global__ void k_norm() {
    int idx  = blockIdx.x * 8 + (threadIdx.x >> 5);
    int lane = threadIdx.x & 31;
    int b = idx / SLOT, j = idx % SLOT;
    uint4* dst = (uint4*)(g_ph + (size_t)idx * Dn);   // 32 lanes x 16B = 512B row
    if (j >= g_nuniq[b]) {
        dst[lane] = make_uint4(0, 0, 0, 0);
        return;
    }
    int c  = g_cnt[b*SLOT + j];
    int st = g_cstart[b*SLOT + j];
    float acc[8];
    #pragma unroll
    for (int q = 0; q < 8; q++) acc[q] = 0.f;
    for (int m = 0; m < c; m++) {
        int r = g_sorted[b*Rn + st + m];
        uint4 v = ((const uint4*)(g_xh + (size_t)(b*Rn + r) * Dn))[lane];
        uint32_t w[4] = {v.x, v.y, v.z, v.w};
        #pragma unroll
        for (int q = 0; q < 4; q++) {
            float2 f = __bfloat1622float2(*(__nv_bfloat162*)&w[q]);
            acc[q*2]   += f.x;
            acc[q*2+1] += f.y;
        }
    }
    float ss = 0.f;
    #pragma unroll
    for (int q = 0; q < 8; q++) ss += acc[q]*acc[q];
    #pragma unroll
    for (int o = 16; o > 0; o >>= 1) ss += __shfl_xor_sync(0xffffffffu, ss, o);
    float cf = (float)c;
    float scale = 1.0f / (cf * fmaxf(sqrtf(ss) / cf, 1e-12f));
    uint32_t o0, o1, o2, o3;
    {
        __nv_bfloat162 p0 = __floats2bfloat162_rn(acc[0]*scale, acc[1]*scale);
        __nv_bfloat162 p1 = __floats2bfloat162_rn(acc[2]*scale, acc[3]*scale);
        __nv_bfloat162 p2 = __floats2bfloat162_rn(acc[4]*scale, acc[5]*scale);
        __nv_bfloat162 p3 = __floats2bfloat162_rn(acc[6]*scale, acc[7]*scale);
        o0 = *(uint32_t*)&p0; o1 = *(uint32_t*)&p1; o2 = *(uint32_t*)&p2; o3 = *(uint32_t*)&p3;
    }
    dst[lane] = make_uint4(o0, o1, o2, o3);
}

// ---------------- 3: bf16 mma.sync GEMM (cp.async 2-stage) + fused softmax partials --
__global__ __launch_bounds__(256, 2) void k_gemm_mma() {
    extern __shared__ __nv_bfloat16 smem[];      // [2][sA 128*PAD | sB 128*PAD]
    __shared__ int   s_jt[128];
    __shared__ float s_m[4][128];
    __shared__ float s_s[4][128];
    int tid = threadIdx.x;
    int warp = tid >> 5, lane = tid & 31;
    int b = blockIdx.z;
    int rBase = blockIdx.y * 128;
    int jBase = blockIdx.x * 128;
    const __nv_bfloat16* A  = g_xh + ((size_t)b*Rn   + rBase) * Dn;
    const __nv_bfloat16* Bp = g_ph + ((size_t)b*SLOT + jBase) * Dn;

    if (tid < 128) s_jt[tid] = g_rslot[b*Rn + rBase + tid];

    int wm = (warp >> 2) * 64;      // 0 / 64
    int wn = (warp & 3) * 32;       // 0 / 32 / 64 / 96
    int wq = warp & 3;

    float acc[4][4][4];
    #pragma unroll
    for (int mt = 0; mt < 4; mt++)
        #pragma unroll
        for (int nt = 0; nt < 4; nt++)
            #pragma unroll
            for (int q = 0; q < 4; q++) acc[mt][nt][q] = 0.f;

    uint32_t sBase = smem_u32(smem);
    const uint32_t stageBytes = 2u * STAGE_ELE * 2u;  // A+B per stage
    const uint32_t sBoff = STAGE_ELE * 2u;

    int aRow = (lane & 15);
    int aColOff = (lane >> 4) * 8;
    int bN = (lane & 7) + ((lane >> 4) << 3);
    int bKOff = ((lane >> 3) & 1) * 8;

    int srow[4], scol[4];
    #pragma unroll
    for (int jj = 0; jj < 4; jj++) {
        int i = tid + jj*256;
        srow[jj] = i >> 3; scol[jj] = i & 7;
    }

    #define ISSUE(kc, stg) { \
        uint32_t d0 = sBase + (stg)*stageBytes; \
        _Pragma("unroll") \
        for (int jj = 0; jj < 4; jj++) { \
            uint32_t off = (srow[jj]*PAD + scol[jj]*8) * 2; \
            cp16(d0 + off,          A  + (size_t)srow[jj]*Dn + (kc)*64 + scol[jj]*8); \
            cp16(d0 + sBoff + off,  Bp + (size_t)srow[jj]*Dn + (kc)*64 + scol[jj]*8); \
        } \
        cp_commit(); \
    }

    ISSUE(0, 0);
    for (int kc = 0; kc < 4; kc++) {
        if (kc) __syncthreads();
        if (kc < 3) ISSUE(kc + 1, (kc + 1) & 1);
        if (kc < 3) cp_wait<1>(); else cp_wait<0>();
        __syncthreads();
        uint32_t sAu = sBase + (kc & 1)*stageBytes;
        uint32_t sBu = sAu + sBoff;
        #pragma unroll
        for (int ks = 0; ks < 4; ks++) {
            int kk = ks * 16;
            uint32_t a[4][4];
            #pragma unroll
            for (int mt = 0; mt < 4; mt++) {
                int row = wm + mt*16 + aRow;
                ldm_x4(a[mt], sAu + (row*PAD + kk + aColOff) * 2);
            }
            uint32_t bb[2][4];
            #pragma unroll
            for (int p = 0; p < 2; p++) {
                int n = wn + p*16 + bN;
                ldm_x4(bb[p], sBu + (n*PAD + kk + bKOff) * 2);
            }
            #pragma unroll
            for (int mt = 0; mt < 4; mt++)
                #pragma unroll
                for (int nt = 0; nt < 4; nt++)
                    mma_bf16(acc[mt][nt], a[mt],
                             bb[nt >> 1][(nt & 1)*2], bb[nt >> 1][(nt & 1)*2 + 1]);
        }
    }

    // ---- fused epilogue: per-row partial (max, sumexp) over this 128-col chunk ----
    int nu = g_nuniq[b];
    int tg = lane >> 2, ti = lane & 3;
    #pragma unroll
    for (int mt = 0; mt < 4; mt++) {
        #pragma unroll
        for (int h = 0; h < 2; h++) {
            int rowL = wm + mt*16 + tg + h*8;
            int jt = s_jt[rowL];
            float vals[8];
            float vmax = -1e30f;
            #pragma unroll
            for (int nt = 0; nt < 4; nt++) {
                #pragma unroll
                for (int ql = 0; ql < 2; ql++) {
                    int j = jBase + wn + nt*8 + ti*2 + ql;
                    float v = acc[mt][nt][h*2 + ql];
                    if (j == jt) g_tgt[b*Rn + rBase + rowL] = v;
                    float vv = (j < nu) ? v : -1e30f;
                    vals[nt*2 + ql] = vv;
                    vmax = fmaxf(vmax, vv);
                }
            }
            vmax = fmaxf(vmax, __shfl_xor_sync(0xffffffffu, vmax, 1));
            vmax = fmaxf(vmax, __shfl_xor_sync(0xffffffffu, vmax, 2));
            float se = 0.f;
            #pragma unroll
            for (int q = 0; q < 8; q++) se += __expf(vals[q] - vmax);
            se += __shfl_xor_sync(0xffffffffu, se, 1);
            se += __shfl_xor_sync(0xffffffffu, se, 2);
            if (ti == 0) { s_m[wq][rowL] = vmax; s_s[wq][rowL] = se; }
        }
    }
    __syncthreads();
    if (tid < 128) {
        float m0 = s_m[0][tid], m1 = s_m[1][tid], m2 = s_m[2][tid], m3 = s_m[3][tid];
        float m = fmaxf(fmaxf(m0, m1), fmaxf(m2, m3));
        float s = s_s[0][tid]*__expf(m0 - m) + s_s[1][tid]*__expf(m1 - m)
                + s_s[2][tid]*__expf(m2 - m) + s_s[3][tid]*__expf(m3 - m);
        int roi = b*Rn + rBase + tid;
        g_pm[roi*4 + blockIdx.x] = m;
        g_ps[roi*4 + blockIdx.x] = s;
    }
}

// ---------------- 4a: per-image NLL partial reduce (one block per image) ----------
__global__ void k_nll_part() {
    __shared__ float ssum[16];
    __shared__ int   scnt[16];
    int b = blockIdx.x;
    int tid = threadIdx.x;                 // 512 threads, one per ROI
    int i = b*Rn + tid;
    float sum = 0.f; int cnt = 0;
    int jt = g_rslot[i];
    if (jt >= 0) {
        float4 pm = *(const float4*)&g_pm[i*4];
        float4 ps = *(const float4*)&g_ps[i*4];
        float m = fmaxf(fmaxf(pm.x, pm.y), fmaxf(pm.z, pm.w));
        float s = ps.x*__expf(pm.x - m) + ps.y*__expf(pm.y - m)
                + ps.z*__expf(pm.z - m) + ps.w*__expf(pm.w - m);
        sum = (m + logf(s)) - g_tgt[i];
        cnt = 1;
    }
    #pragma unroll
    for (int o = 16; o > 0; o >>= 1) {
        sum += __shfl_xor_sync(0xffffffffu, sum, o);
        cnt += __shfl_xor_sync(0xffffffffu, cnt, o);
    }
    if ((tid & 31) == 0) { ssum[tid >> 5] = sum; scnt[tid >> 5] = cnt; }
    __syncthreads();
    if (tid == 0) {
        float ts = 0.f; int tc = 0;
        #pragma unroll
        for (int w = 0; w < 16; w++) { ts += ssum[w]; tc += scnt[w]; }
        g_bsum[b] = ts; g_bcnt[b] = tc;
    }
}

// ---------------- 4b: combine 32 per-image partials ----------------
__global__ void k_final(float* __restrict__ out) {
    int lane = threadIdx.x;                // 32 threads
    float s = g_bsum[lane];
    int   c = g_bcnt[lane];
    #pragma unroll
    for (int o = 16; o > 0; o >>= 1) {
        s += __shfl_xor_sync(0xffffffffu, s, o);
        c += __shfl_xor_sync(0xffffffffu, c, o);
    }
    if (lane == 0)
        out[0] = s / fmaxf((float)c, 1.0f);
}

extern "C" void kernel_launch(void* const* d_in, const int* in_sizes, int n_in,
                              void* d_out, int out_size) {
    const float* inp = (const float*)d_in[0];
    const float* cls = (const float*)d_in[1];
    const int*   lab = (const int*)d_in[2];
    float* out = (float*)d_out;

    const int gemmSmem = 2 * 2 * STAGE_ELE * 2;  // 73728 bytes
    cudaFuncSetAttribute(k_gemm_mma, cudaFuncAttributeMaxDynamicSharedMemorySize, gemmSmem);

    k_prep_compact<<<Bn + NROWS*Dn/4/1024, 256>>>(inp, cls, lab);
    k_norm<<<Bn*SLOT/8, 256>>>();
    k_gemm_mma<<<dim3(SLOT/128, Rn/128, Bn), 256, gemmSmem>>>();
    k_nll_part<<<Bn, Rn>>>();
    k_final<<<1, 32>>>(out);
}